// round 7
// baseline (speedup 1.0000x reference)
#include <cuda_runtime.h>
#include <stdint.h>

// Inputs (metadata order):
//   d_in[0] disp        float32 [E,3]   (E = 3,200,000)
//   d_in[1] a           float32 [E]
//   d_in[2] b           float32 [E]
//   d_in[3] edge_index  int32   [2,E]   row0 = src, row1 = dst
//   d_in[4] atom_node   int32   [N]     (N = 100,000)
// Output: float32 [N,3]
//
// force_edge = 2*(b*exp(-r2) - a) * disp ;  out = scatter(+,src) - scatter(+,dst)
//
// Pipeline: memset scratch -> 4-edge/thread vectorized scatter (float4 RED) ->
//           4-atom/thread float4 gather to [N,3].

#define N_MAX 100352  // >= 100000

__device__ float4 g_accum[N_MAX];

__device__ __forceinline__ void do_edge(float dx, float dy, float dz,
                                        float ae, float be, int si, int di) {
    float r2 = fmaf(dx, dx, fmaf(dy, dy, dz * dz));
    float s = 2.0f * fmaf(be, __expf(-r2), -ae);  // 2*(b*exp(-r2) - a)
    float fx = s * dx, fy = s * dy, fz = s * dz;
    atomicAdd(&g_accum[si], make_float4( fx,  fy,  fz, 0.f));
    atomicAdd(&g_accum[di], make_float4(-fx, -fy, -fz, 0.f));
}

__global__ __launch_bounds__(256)
void edge_force_scatter4_kernel(const float* __restrict__ disp,
                                const float* __restrict__ a,
                                const float* __restrict__ b,
                                const int* __restrict__ src,
                                const int* __restrict__ dst,
                                int num_edges) {
    int i = blockIdx.x * blockDim.x + threadIdx.x;
    int e0 = i * 4;
    if (e0 + 3 < num_edges) {
        const float4* d4 = (const float4*)(disp + 3 * e0);  // 48B-aligned
        float4 p0 = d4[0];
        float4 p1 = d4[1];
        float4 p2 = d4[2];
        float4 av = *(const float4*)(a + e0);
        float4 bv = *(const float4*)(b + e0);
        int4   sv = *(const int4*)(src + e0);
        int4   dv = *(const int4*)(dst + e0);

        do_edge(p0.x, p0.y, p0.z, av.x, bv.x, sv.x, dv.x);
        do_edge(p0.w, p1.x, p1.y, av.y, bv.y, sv.y, dv.y);
        do_edge(p1.z, p1.w, p2.x, av.z, bv.z, sv.z, dv.z);
        do_edge(p2.y, p2.z, p2.w, av.w, bv.w, sv.w, dv.w);
    } else {
        for (int e = e0; e < num_edges; e++) {
            do_edge(disp[3 * e + 0], disp[3 * e + 1], disp[3 * e + 2],
                    a[e], b[e], src[e], dst[e]);
        }
    }
}

// 4 atoms per thread: read 4 x float4 from scratch, write 3 x float4 to out.
__global__ void gather_out4_kernel(float4* __restrict__ out4, int n_quads) {
    int t = blockIdx.x * blockDim.x + threadIdx.x;
    if (t >= n_quads) return;
    int i = 4 * t;
    float4 v0 = g_accum[i + 0];
    float4 v1 = g_accum[i + 1];
    float4 v2 = g_accum[i + 2];
    float4 v3 = g_accum[i + 3];
    out4[3 * t + 0] = make_float4(v0.x, v0.y, v0.z, v1.x);
    out4[3 * t + 1] = make_float4(v1.y, v1.z, v2.x, v2.y);
    out4[3 * t + 2] = make_float4(v2.z, v3.x, v3.y, v3.z);
}

__global__ void gather_out_tail_kernel(float* __restrict__ out, int start, int n) {
    int i = start + blockIdx.x * blockDim.x + threadIdx.x;
    if (i < n) {
        float4 v = g_accum[i];
        out[3 * i + 0] = v.x;
        out[3 * i + 1] = v.y;
        out[3 * i + 2] = v.z;
    }
}

extern "C" void kernel_launch(void* const* d_in, const int* in_sizes, int n_in,
                              void* d_out, int out_size) {
    const float* disp = (const float*)d_in[0];
    const float* a    = (const float*)d_in[1];
    const float* b    = (const float*)d_in[2];
    const int*   ei   = (const int*)d_in[3];   // int32 [2, E]

    int num_edges = in_sizes[1];               // a is [E]
    const int* src = ei;
    const int* dst = ei + num_edges;

    float* out = (float*)d_out;
    int n_atoms = out_size / 3;

    // Zero scratch via memset node (graph-capturable, no kernel overhead).
    void* accum_ptr = nullptr;
    cudaGetSymbolAddress(&accum_ptr, g_accum);
    cudaMemsetAsync(accum_ptr, 0, (size_t)n_atoms * sizeof(float4));

    {
        int threads = 256;
        int nthreads = (num_edges + 3) / 4;
        int blocks = (nthreads + threads - 1) / threads;
        edge_force_scatter4_kernel<<<blocks, threads>>>(disp, a, b, src, dst,
                                                        num_edges);
    }

    int n_quads = n_atoms / 4;
    {
        int threads = 256;
        int blocks = (n_quads + threads - 1) / threads;
        gather_out4_kernel<<<blocks, threads>>>((float4*)out, n_quads);
    }
    int tail_start = n_quads * 4;
    if (tail_start < n_atoms) {
        int tail = n_atoms - tail_start;
        gather_out_tail_kernel<<<(tail + 255) / 256, 256>>>(out, tail_start, n_atoms);
    }
}